// round 3
// baseline (speedup 1.0000x reference)
#include <cuda_runtime.h>

// MMD_53008486367839 — batched persistence-diagram MMD with RBF kernel.
// B=64 diagrams, N=M=1024 points each, WIDTH=1, DECAY=1.
//
// Algebraic form used here: combine X (signed weight +lifetime) and Y
// (signed weight -lifetime) into one set of P=2048 points per batch:
//     mmd_b = sum_{i,j} s_i s_j exp(-d2(p_i, p_j))
//           = S_XX - 2 S_XY + S_YY            (exactly)
// Coordinates are pre-scaled by sqrt(log2 e) so the inner loop computes
// ex2.approx(-(du^2+dv^2)) with no extra multiply. d2 >= 0 by construction
// so the reference's fmaxf clamp is a no-op.

#define BATCH 64
#define NPTS  1024
#define MPTS  1024
#define P     2048   // NPTS + MPTS
#define RBLKS 8      // row-blocks per batch (2048 rows / 256 threads)

// Scratch (no cudaMalloc allowed): 64*2048*16B = 2 MB point buffer + accumulators.
__device__ float4 g_pts[BATCH * P];
__device__ float  g_bacc[BATCH];

__device__ __forceinline__ float ex2_approx(float x) {
    float y;
    asm("ex2.approx.ftz.f32 %0, %1;" : "=f"(y) : "f"(x));
    return y;
}

// ---------------------------------------------------------------------------
// Kernel 1: build scaled, signed point set; zero per-batch accumulators.
// Runs every launch -> graph replays are deterministic.
// ---------------------------------------------------------------------------
__global__ void __launch_bounds__(256) mmd_prep(const float* __restrict__ X,
                                                const float* __restrict__ Y) {
    int idx = blockIdx.x * blockDim.x + threadIdx.x;   // over BATCH*P
    if (idx < BATCH) g_bacc[idx] = 0.0f;
    if (idx >= BATCH * P) return;

    int b = idx >> 11;          // / P
    int p = idx & (P - 1);      // % P

    const float SC = 1.2011224087864498f;  // sqrt(log2(e)) = sqrt(1.4426950408889634)

    float birth, death, sgn;
    if (p < NPTS) {
        const float* x = X + ((size_t)b * NPTS + p) * 2;
        birth = x[0]; death = x[1]; sgn = 1.0f;
    } else {
        const float* y = Y + ((size_t)b * MPTS + (p - NPTS)) * 2;
        birth = y[0]; death = y[1]; sgn = -1.0f;
    }
    float lt = death - birth;                 // lifetime (= decay weight, DECAY=1)
    g_pts[idx] = make_float4(SC * birth, SC * lt, sgn * lt, 0.0f);
}

// ---------------------------------------------------------------------------
// Kernel 2: main pairwise kernel-sum. One block = 256 rows of one batch.
// Batch's full 2048-point set staged in shared (32 KB), broadcast reads.
// ---------------------------------------------------------------------------
__global__ void __launch_bounds__(256) mmd_main() {
    __shared__ float4 sh[P];                  // 32 KB
    __shared__ float  warp_sums[8];

    int b    = blockIdx.x / RBLKS;
    int rblk = blockIdx.x % RBLKS;

    const float4* pts = g_pts + b * P;
    #pragma unroll
    for (int i = 0; i < P / 256; i++)
        sh[threadIdx.x + i * 256] = pts[threadIdx.x + i * 256];
    __syncthreads();

    int row = rblk * 256 + threadIdx.x;
    float4 me = sh[row];
    const float u = me.x, v = me.y, s_i = me.z;

    float a0 = 0.f, a1 = 0.f, a2 = 0.f, a3 = 0.f;

    #pragma unroll 2
    for (int j = 0; j < P; j += 4) {
        float4 p0 = sh[j + 0];
        float4 p1 = sh[j + 1];
        float4 p2 = sh[j + 2];
        float4 p3 = sh[j + 3];

        float du0 = u - p0.x, dv0 = v - p0.y;
        float du1 = u - p1.x, dv1 = v - p1.y;
        float du2 = u - p2.x, dv2 = v - p2.y;
        float du3 = u - p3.x, dv3 = v - p3.y;

        // d2n = -(du^2 + dv^2), negations fold into FMUL/FFMA src modifiers
        float d2n0 = fmaf(du0, -du0, -(dv0 * dv0));
        float d2n1 = fmaf(du1, -du1, -(dv1 * dv1));
        float d2n2 = fmaf(du2, -du2, -(dv2 * dv2));
        float d2n3 = fmaf(du3, -du3, -(dv3 * dv3));

        a0 = fmaf(p0.z, ex2_approx(d2n0), a0);
        a1 = fmaf(p1.z, ex2_approx(d2n1), a1);
        a2 = fmaf(p2.z, ex2_approx(d2n2), a2);
        a3 = fmaf(p3.z, ex2_approx(d2n3), a3);
    }

    float acc = ((a0 + a1) + (a2 + a3)) * s_i;

    // intra-warp reduce
    #pragma unroll
    for (int o = 16; o > 0; o >>= 1)
        acc += __shfl_down_sync(0xFFFFFFFFu, acc, o);

    int lane = threadIdx.x & 31, wid = threadIdx.x >> 5;
    if (lane == 0) warp_sums[wid] = acc;
    __syncthreads();

    if (threadIdx.x == 0) {
        float bs = 0.f;
        #pragma unroll
        for (int w = 0; w < 8; w++) bs += warp_sums[w];
        atomicAdd(&g_bacc[b], bs);
    }
}

// ---------------------------------------------------------------------------
// Kernel 3: finalize  out = sum_b g_bacc[b] * weights[b] / num_samples[b]^2
// ---------------------------------------------------------------------------
__global__ void mmd_finalize(const float* __restrict__ weights,
                             const float* __restrict__ num_samples,
                             float* __restrict__ out) {
    __shared__ float sv[2];
    int t = threadIdx.x;                      // 64 threads
    float v = 0.f;
    if (t < BATCH) {
        float ns = num_samples[t];
        v = g_bacc[t] * weights[t] / (ns * ns);
    }
    #pragma unroll
    for (int o = 16; o > 0; o >>= 1)
        v += __shfl_down_sync(0xFFFFFFFFu, v, o);
    if ((t & 31) == 0) sv[t >> 5] = v;
    __syncthreads();
    if (t == 0) out[0] = sv[0] + sv[1];
}

// ---------------------------------------------------------------------------
extern "C" void kernel_launch(void* const* d_in, const int* in_sizes, int n_in,
                              void* d_out, int out_size) {
    const float* X  = (const float*)d_in[0];  // [64,1024,2]
    const float* Y  = (const float*)d_in[1];  // [64,1024,2]
    const float* w  = (const float*)d_in[2];  // [64]
    const float* ns = (const float*)d_in[3];  // [64]
    float* out = (float*)d_out;

    mmd_prep<<<(BATCH * P + 255) / 256, 256>>>(X, Y);
    mmd_main<<<BATCH * RBLKS, 256>>>();
    mmd_finalize<<<1, 64>>>(w, ns, out);
}

// round 5
// speedup vs baseline: 2.1852x; 2.1852x over previous
#include <cuda_runtime.h>

// MMD_53008486367839 — batched persistence-diagram MMD with RBF kernel.
// B=64, N=M=1024, WIDTH=DECAY=1.
//
// mmd_b = sum_{i,j} s_i s_j exp(-d2(p_i,p_j)) over the merged signed set
// (X with +lifetime, Y with -lifetime), P=2048 points per batch.
// R3: (a) symmetric triangular tiling — 36 of 64 tiles (off-diag ×2);
//     (b) packed f32x2 distance math — MUFU.EX2 becomes the binding pipe.
// Coords pre-scaled by sqrt(log2 e) so EX2 input is just -(du^2+dv^2).

#define BATCH 64
#define NPTS  1024
#define P     2048
#define TS    256          // tile side
#define NT    8            // tiles per side (P/TS)
#define NTRI  36           // NT*(NT+1)/2

__device__ float4 g_pts[BATCH * P];
__device__ float  g_bacc[BATCH];

__constant__ unsigned char c_ri[NTRI] =
    {0,0,0,0,0,0,0,0, 1,1,1,1,1,1,1, 2,2,2,2,2,2, 3,3,3,3,3, 4,4,4,4, 5,5,5, 6,6, 7};
__constant__ unsigned char c_cj[NTRI] =
    {0,1,2,3,4,5,6,7, 1,2,3,4,5,6,7, 2,3,4,5,6,7, 3,4,5,6,7, 4,5,6,7, 5,6,7, 6,7, 7};

// ---- packed f32x2 helpers ------------------------------------------------
__device__ __forceinline__ unsigned long long pack2(float lo, float hi) {
    unsigned long long r;
    asm("mov.b64 %0, {%1, %2};" : "=l"(r) : "f"(lo), "f"(hi));
    return r;
}
__device__ __forceinline__ unsigned long long add2(unsigned long long a, unsigned long long b) {
    unsigned long long r;
    asm("add.rn.f32x2 %0, %1, %2;" : "=l"(r) : "l"(a), "l"(b));
    return r;
}
__device__ __forceinline__ unsigned long long mul2(unsigned long long a, unsigned long long b) {
    unsigned long long r;
    asm("mul.rn.f32x2 %0, %1, %2;" : "=l"(r) : "l"(a), "l"(b));
    return r;
}
__device__ __forceinline__ unsigned long long fma2(unsigned long long a, unsigned long long b,
                                                   unsigned long long c) {
    unsigned long long r;
    asm("fma.rn.f32x2 %0, %1, %2, %3;" : "=l"(r) : "l"(a), "l"(b), "l"(c));
    return r;
}
// negate packed d2 (sign-bit xor, off the FMA pipe) and take ex2 of both halves
__device__ __forceinline__ void ex2_pair(unsigned long long d2, float& klo, float& khi) {
    asm("{\n\t"
        ".reg .b64 nd;\n\t"
        ".reg .f32 lo, hi;\n\t"
        "xor.b64 nd, %2, 0x8000000080000000;\n\t"
        "mov.b64 {lo, hi}, nd;\n\t"
        "ex2.approx.ftz.f32 %0, lo;\n\t"
        "ex2.approx.ftz.f32 %1, hi;\n\t"
        "}" : "=f"(klo), "=f"(khi) : "l"(d2));
}
__device__ __forceinline__ unsigned long long lds64(unsigned addr) {
    unsigned long long r;
    asm volatile("ld.shared.b64 %0, [%1];" : "=l"(r) : "r"(addr));
    return r;
}

// ---------------------------------------------------------------------------
// Kernel 1: build scaled, signed point set; zero per-batch accumulators.
// ---------------------------------------------------------------------------
__global__ void __launch_bounds__(256) mmd_prep(const float* __restrict__ X,
                                                const float* __restrict__ Y) {
    int idx = blockIdx.x * blockDim.x + threadIdx.x;
    if (idx < BATCH) g_bacc[idx] = 0.0f;
    if (idx >= BATCH * P) return;

    int b = idx >> 11;
    int p = idx & (P - 1);
    const float SC = 1.2011224087864498f;  // sqrt(log2 e)

    float birth, death, sgn;
    if (p < NPTS) {
        const float* x = X + ((size_t)b * NPTS + p) * 2;
        birth = x[0]; death = x[1]; sgn = 1.0f;
    } else {
        const float* y = Y + ((size_t)b * NPTS + (p - NPTS)) * 2;
        birth = y[0]; death = y[1]; sgn = -1.0f;
    }
    float lt = death - birth;
    g_pts[idx] = make_float4(SC * birth, SC * lt, sgn * lt, 0.0f);
}

// ---------------------------------------------------------------------------
// Kernel 2: one block = one (batch, triangular tile). 256 threads, each owns
// one row of the 256x256 tile; 256-column tile staged in shared SoA
// (x pairs, y pairs, signed weight pairs) for ld.shared.b64 packed reads.
// ---------------------------------------------------------------------------
__global__ void __launch_bounds__(256) mmd_main() {
    __shared__ float sx[TS];     // column x (SC-scaled)
    __shared__ float sy[TS];     // column y
    __shared__ float sw[TS];     // column signed weight
    __shared__ float warp_sums[8];

    int b = blockIdx.x / NTRI;
    int t = blockIdx.x - b * NTRI;
    int ri = c_ri[t];
    int cj = c_cj[t];

    const float4* base = g_pts + b * P;

    // stage column tile (store x,y directly; sign-handling via xor in ex2_pair)
    float4 cp = base[cj * TS + threadIdx.x];
    sx[threadIdx.x] = cp.x;
    sy[threadIdx.x] = cp.y;
    sw[threadIdx.x] = cp.z;

    float4 me = base[ri * TS + threadIdx.x];
    __syncthreads();

    // packed per-thread constants: (-u,-u), (-v,-v) so du2 = add2(nu2, x2)
    unsigned long long nu2 = pack2(-me.x, -me.x);
    unsigned long long nv2 = pack2(-me.y, -me.y);

    unsigned ax = (unsigned)__cvta_generic_to_shared(sx);
    unsigned ay = (unsigned)__cvta_generic_to_shared(sy);
    unsigned aw = (unsigned)__cvta_generic_to_shared(sw);

    float a0 = 0.f, a1 = 0.f, a2 = 0.f, a3 = 0.f;

    #pragma unroll 4
    for (int j = 0; j < TS / 2; j += 4) {      // 4 packed groups = 8 pairs / iter
        #pragma unroll
        for (int g = 0; g < 4; g++) {
            unsigned off = (unsigned)((j + g) * 8);
            unsigned long long x2 = lds64(ax + off);
            unsigned long long y2 = lds64(ay + off);
            unsigned long long w2 = lds64(aw + off);

            unsigned long long du = add2(nu2, x2);         // (x-u) ; square is same
            unsigned long long dv = add2(nv2, y2);
            unsigned long long d2 = fma2(du, du, mul2(dv, dv));  // >= 0

            float klo, khi;
            ex2_pair(d2, klo, khi);                        // exp(-d2) both halves

            float wlo = __uint_as_float((unsigned)w2);
            float whi = __uint_as_float((unsigned)(w2 >> 32));
            float* acc = (g == 0) ? &a0 : (g == 1) ? &a1 : (g == 2) ? &a2 : &a3;
            *acc = fmaf(wlo, klo, *acc);
            *acc = fmaf(whi, khi, *acc);
        }
    }

    float scale = (ri == cj) ? 1.0f : 2.0f;
    float acc = ((a0 + a1) + (a2 + a3)) * (me.z * scale);

    #pragma unroll
    for (int o = 16; o > 0; o >>= 1)
        acc += __shfl_down_sync(0xFFFFFFFFu, acc, o);

    int lane = threadIdx.x & 31, wid = threadIdx.x >> 5;
    if (lane == 0) warp_sums[wid] = acc;
    __syncthreads();

    if (threadIdx.x == 0) {
        float bs = 0.f;
        #pragma unroll
        for (int w = 0; w < 8; w++) bs += warp_sums[w];
        atomicAdd(&g_bacc[b], bs);
    }
}

// ---------------------------------------------------------------------------
// Kernel 3: finalize  out = sum_b g_bacc[b] * weights[b] / num_samples[b]^2
// ---------------------------------------------------------------------------
__global__ void mmd_finalize(const float* __restrict__ weights,
                             const float* __restrict__ num_samples,
                             float* __restrict__ out) {
    __shared__ float sv[2];
    int t = threadIdx.x;
    float v = 0.f;
    if (t < BATCH) {
        float ns = num_samples[t];
        v = g_bacc[t] * weights[t] / (ns * ns);
    }
    #pragma unroll
    for (int o = 16; o > 0; o >>= 1)
        v += __shfl_down_sync(0xFFFFFFFFu, v, o);
    if ((t & 31) == 0) sv[t >> 5] = v;
    __syncthreads();
    if (t == 0) out[0] = sv[0] + sv[1];
}

// ---------------------------------------------------------------------------
extern "C" void kernel_launch(void* const* d_in, const int* in_sizes, int n_in,
                              void* d_out, int out_size) {
    const float* X  = (const float*)d_in[0];
    const float* Y  = (const float*)d_in[1];
    const float* w  = (const float*)d_in[2];
    const float* ns = (const float*)d_in[3];
    float* out = (float*)d_out;

    mmd_prep<<<(BATCH * P + 255) / 256, 256>>>(X, Y);
    mmd_main<<<BATCH * NTRI, 256>>>();
    mmd_finalize<<<1, 64>>>(w, ns, out);
}

// round 6
// speedup vs baseline: 2.1971x; 1.0054x over previous
#include <cuda_runtime.h>

// MMD_53008486367839 — batched persistence-diagram MMD with RBF kernel.
// B=64, N=M=1024, WIDTH=DECAY=1.
//
// mmd_b = sum_{i,j} s_i s_j exp(-d2(p_i,p_j)) over the merged signed set
// (X with +lifetime, Y with -lifetime), P=2048 points per batch.
//   - symmetric triangular tiling: 36 of 64 tiles (off-diag contributions x2)
//   - packed f32x2 distance math: MUFU.EX2 is the binding pipe
//   - coords pre-scaled by sqrt(log2 e) so EX2 input is -(du^2+dv^2) directly
// R6: fully fused — prep (point transform) inlined into the tile staging,
//     finalize folded into a per-block atomicAdd of w[b]/ns^2-scaled sums
//     into out[0]. Only a trivial zeroing kernel remains besides main.

#define BATCH 64
#define NPTS  1024
#define P     2048
#define TS    256          // tile side
#define NT    8            // tiles per side (P/TS)
#define NTRI  36           // NT*(NT+1)/2

__constant__ unsigned char c_ri[NTRI] =
    {0,0,0,0,0,0,0,0, 1,1,1,1,1,1,1, 2,2,2,2,2,2, 3,3,3,3,3, 4,4,4,4, 5,5,5, 6,6, 7};
__constant__ unsigned char c_cj[NTRI] =
    {0,1,2,3,4,5,6,7, 1,2,3,4,5,6,7, 2,3,4,5,6,7, 3,4,5,6,7, 4,5,6,7, 5,6,7, 6,7, 7};

// ---- packed f32x2 helpers ------------------------------------------------
__device__ __forceinline__ unsigned long long pack2(float lo, float hi) {
    unsigned long long r;
    asm("mov.b64 %0, {%1, %2};" : "=l"(r) : "f"(lo), "f"(hi));
    return r;
}
__device__ __forceinline__ unsigned long long add2(unsigned long long a, unsigned long long b) {
    unsigned long long r;
    asm("add.rn.f32x2 %0, %1, %2;" : "=l"(r) : "l"(a), "l"(b));
    return r;
}
__device__ __forceinline__ unsigned long long mul2(unsigned long long a, unsigned long long b) {
    unsigned long long r;
    asm("mul.rn.f32x2 %0, %1, %2;" : "=l"(r) : "l"(a), "l"(b));
    return r;
}
__device__ __forceinline__ unsigned long long fma2(unsigned long long a, unsigned long long b,
                                                   unsigned long long c) {
    unsigned long long r;
    asm("fma.rn.f32x2 %0, %1, %2, %3;" : "=l"(r) : "l"(a), "l"(b), "l"(c));
    return r;
}
// negate packed d2 (sign-bit xor, off the FMA pipe) and take ex2 of both halves
__device__ __forceinline__ void ex2_pair(unsigned long long d2, float& klo, float& khi) {
    asm("{\n\t"
        ".reg .b64 nd;\n\t"
        ".reg .f32 lo, hi;\n\t"
        "xor.b64 nd, %2, 0x8000000080000000;\n\t"
        "mov.b64 {lo, hi}, nd;\n\t"
        "ex2.approx.ftz.f32 %0, lo;\n\t"
        "ex2.approx.ftz.f32 %1, hi;\n\t"
        "}" : "=f"(klo), "=f"(khi) : "l"(d2));
}
__device__ __forceinline__ unsigned long long lds64(unsigned addr) {
    unsigned long long r;
    asm volatile("ld.shared.b64 %0, [%1];" : "=l"(r) : "r"(addr));
    return r;
}

// Load point p (0..P-1) of batch b straight from X/Y and transform:
// returns (SC*birth, SC*lifetime, sign*lifetime).
__device__ __forceinline__ float3 load_pt(const float* __restrict__ X,
                                          const float* __restrict__ Y,
                                          int b, int p) {
    const float SC = 1.2011224087864498f;   // sqrt(log2 e)
    float birth, death, sgn;
    if (p < NPTS) {
        const float2 xy = __ldg((const float2*)(X + ((size_t)b * NPTS + p) * 2));
        birth = xy.x; death = xy.y; sgn = 1.0f;
    } else {
        const float2 xy = __ldg((const float2*)(Y + ((size_t)b * NPTS + (p - NPTS)) * 2));
        birth = xy.x; death = xy.y; sgn = -1.0f;
    }
    float lt = death - birth;
    return make_float3(SC * birth, SC * lt, sgn * lt);
}

// ---------------------------------------------------------------------------
// Kernel 0: zero the (poisoned) output scalar.
// ---------------------------------------------------------------------------
__global__ void mmd_zero(float* __restrict__ out) { out[0] = 0.0f; }

// ---------------------------------------------------------------------------
// Kernel 1: fused main. One block = one (batch, triangular tile).
// 256 threads; each owns one row of the 256x256 tile. Column tile staged in
// shared SoA (x / y / signed-weight) for packed ld.shared.b64 reads.
// Block result scaled by w[b]/ns^2 and atomically added to out[0].
// ---------------------------------------------------------------------------
__global__ void __launch_bounds__(256) mmd_main(const float* __restrict__ X,
                                                const float* __restrict__ Y,
                                                const float* __restrict__ weights,
                                                const float* __restrict__ num_samples,
                                                float* __restrict__ out) {
    __shared__ float sx[TS];     // column x (SC-scaled)
    __shared__ float sy[TS];     // column y
    __shared__ float sw[TS];     // column signed weight
    __shared__ float warp_sums[8];

    int b = blockIdx.x / NTRI;
    int t = blockIdx.x - b * NTRI;
    int ri = c_ri[t];
    int cj = c_cj[t];

    // stage column tile (transform fused in)
    float3 cp = load_pt(X, Y, b, cj * TS + threadIdx.x);
    sx[threadIdx.x] = cp.x;
    sy[threadIdx.x] = cp.y;
    sw[threadIdx.x] = cp.z;

    // row point for this thread
    float3 me = load_pt(X, Y, b, ri * TS + threadIdx.x);
    __syncthreads();

    // packed per-thread constants: (-u,-u), (-v,-v) so du = add2(nu2, x2)
    unsigned long long nu2 = pack2(-me.x, -me.x);
    unsigned long long nv2 = pack2(-me.y, -me.y);

    unsigned ax = (unsigned)__cvta_generic_to_shared(sx);
    unsigned ay = (unsigned)__cvta_generic_to_shared(sy);
    unsigned aw = (unsigned)__cvta_generic_to_shared(sw);

    float a0 = 0.f, a1 = 0.f, a2 = 0.f, a3 = 0.f;

    #pragma unroll 4
    for (int j = 0; j < TS / 2; j += 4) {      // 4 packed groups = 8 pairs / iter
        #pragma unroll
        for (int g = 0; g < 4; g++) {
            unsigned off = (unsigned)((j + g) * 8);
            unsigned long long x2 = lds64(ax + off);
            unsigned long long y2 = lds64(ay + off);
            unsigned long long w2 = lds64(aw + off);

            unsigned long long du = add2(nu2, x2);               // x - u
            unsigned long long dv = add2(nv2, y2);               // y - v
            unsigned long long d2 = fma2(du, du, mul2(dv, dv));  // >= 0

            float klo, khi;
            ex2_pair(d2, klo, khi);                              // exp(-d2), both

            float wlo = __uint_as_float((unsigned)w2);
            float whi = __uint_as_float((unsigned)(w2 >> 32));
            float* acc = (g == 0) ? &a0 : (g == 1) ? &a1 : (g == 2) ? &a2 : &a3;
            *acc = fmaf(wlo, klo, *acc);
            *acc = fmaf(whi, khi, *acc);
        }
    }

    float scale = (ri == cj) ? 1.0f : 2.0f;
    float acc = ((a0 + a1) + (a2 + a3)) * (me.z * scale);

    #pragma unroll
    for (int o = 16; o > 0; o >>= 1)
        acc += __shfl_down_sync(0xFFFFFFFFu, acc, o);

    int lane = threadIdx.x & 31, wid = threadIdx.x >> 5;
    if (lane == 0) warp_sums[wid] = acc;
    __syncthreads();

    if (threadIdx.x == 0) {
        float bs = 0.f;
        #pragma unroll
        for (int w = 0; w < 8; w++) bs += warp_sums[w];
        float ns = __ldg(&num_samples[b]);
        atomicAdd(out, bs * __ldg(&weights[b]) / (ns * ns));
    }
}

// ---------------------------------------------------------------------------
extern "C" void kernel_launch(void* const* d_in, const int* in_sizes, int n_in,
                              void* d_out, int out_size) {
    const float* X  = (const float*)d_in[0];
    const float* Y  = (const float*)d_in[1];
    const float* w  = (const float*)d_in[2];
    const float* ns = (const float*)d_in[3];
    float* out = (float*)d_out;

    mmd_zero<<<1, 1>>>(out);
    mmd_main<<<BATCH * NTRI, 256>>>(X, Y, w, ns, out);
}

// round 8
// speedup vs baseline: 3.9887x; 1.8155x over previous
#include <cuda_runtime.h>

// MMD_53008486367839 — batched persistence-diagram MMD with RBF kernel.
// B=64, N=M=1024, WIDTH=DECAY=1.
//
// R7: Mercer feature expansion. On the bounded domain u,v in [0,1):
//   K(p,q) = e^{-|p|^2} e^{-|q|^2} e^{2(ux+vy)}
//          = e^{-|p|^2} e^{-|q|^2} * sum_{a+b<=D} (2u x)^a (2v y)^b /(a! b!)
// (positive-coefficient PSD expansion; remainder at D=20 is < 2e-9 pointwise).
// So  mmd_b = sum_{a+b<=D} c_ab * F_ab^2,   c_ab = 2^(a+b)/(a! b!),
//     F_ab  = sum_i s_i e^{-u_i^2-v_i^2} u_i^a v_i^b,
// with s_i = +lifetime for X points, -lifetime for Y points.
// Work: O(B*P*R) FMA instead of O(B*P^2) EX2 — kills the MUFU floor.

#define BATCH 64
#define NPTS  1024
#define P     2048
#define D     20            // total degree of expansion
#define NF    231           // (D+1)(D+2)/2 features
#define PB    4             // blocks per batch
#define PPB   512           // points per block (P/PB)
#define TILE  256           // points per shared tile
#define NPOW  (D + 1)       // 21 power rows
#define STR   260           // padded row stride in words (multiple of 4 -> 16B rows)

__device__ float g_F[BATCH][NF];

__constant__ float c_inv_fact[NPOW] = {
    1.0f, 1.0f, 0.5f, 1.6666666666666666e-01f, 4.1666666666666664e-02f,
    8.3333333333333332e-03f, 1.3888888888888889e-03f, 1.9841269841269841e-04f,
    2.4801587301587302e-05f, 2.7557319223985893e-06f, 2.7557319223985888e-07f,
    2.5052108385441720e-08f, 2.0876756987868100e-09f, 1.6059043836821613e-10f,
    1.1470745597729725e-11f, 7.6471637318198164e-13f, 4.7794773323873853e-14f,
    2.8114572543455206e-15f, 1.5619206968586226e-16f, 8.2206352466243295e-18f,
    4.1103176233121648e-19f};

__device__ __forceinline__ float ex2f_(float x) {
    float y;
    asm("ex2.approx.ftz.f32 %0, %1;" : "=f"(y) : "f"(x));
    return y;
}

// thread index -> (a, b) with a-major enumeration of {a+b<=D}
__device__ __forceinline__ void feat_ab(int k, int& fa, int& fb) {
    int a = 0;
    #pragma unroll 1
    while (k >= (D + 1 - a)) { k -= (D + 1 - a); a++; }
    fa = a; fb = k;
}

// ---------------------------------------------------------------------------
// Kernel 0: zero feature accumulators and the output scalar.
// ---------------------------------------------------------------------------
__global__ void mmd_zero(float* __restrict__ out) {
    int i = blockIdx.x * blockDim.x + threadIdx.x;
    if (i < BATCH * NF) ((float*)g_F)[i] = 0.0f;
    if (i == 0) out[0] = 0.0f;
}

// ---------------------------------------------------------------------------
// Kernel 1: feature sums. Block = (batch, quarter of its 2048 points).
// Phase 1: each thread transforms one point, writes folded power chains
//          spu[a][t] = s*e^{-u^2-v^2} * u^a  and  spv[b][t] = v^b  to shared.
// Phase 2: thread k (k<NF) owns feature (a,b); streams the tile with
//          float4 loads (spu row is warp-broadcast) and 4 FMAs per 4 points.
// ---------------------------------------------------------------------------
__global__ void __launch_bounds__(256) mmd_features(const float* __restrict__ X,
                                                    const float* __restrict__ Y) {
    __shared__ __align__(16) float spu[NPOW][STR];
    __shared__ __align__(16) float spv[NPOW][STR];

    int b     = blockIdx.x / PB;
    int chunk = blockIdx.x % PB;
    int t     = threadIdx.x;

    int fa, fb;
    feat_ab(t < NF ? t : 0, fa, fb);

    float acc0 = 0.f, acc1 = 0.f, acc2 = 0.f, acc3 = 0.f;

    #pragma unroll 1
    for (int tile = 0; tile < PPB / TILE; tile++) {
        // ---- phase 1: transform my point, write power chains ----
        int p = chunk * PPB + tile * TILE + t;
        float u, v, s;
        if (p < NPTS) {
            float2 xy = __ldg((const float2*)(X + ((size_t)b * NPTS + p) * 2));
            u = xy.x; v = xy.y - xy.x; s = v;
        } else {
            float2 xy = __ldg((const float2*)(Y + ((size_t)b * NPTS + (p - NPTS)) * 2));
            u = xy.x; v = xy.y - xy.x; s = -v;
        }
        const float LOG2E = 1.4426950408889634f;
        float m  = fmaf(u, u, v * v);
        float ps = s * ex2f_(-m * LOG2E);       // s * exp(-(u^2+v^2))

        if (tile) __syncthreads();              // previous tile fully consumed

        float pw = ps;
        spu[0][t] = pw;
        #pragma unroll
        for (int a = 1; a < NPOW; a++) { pw *= u; spu[a][t] = pw; }
        pw = 1.f;
        spv[0][t] = 1.f;
        #pragma unroll
        for (int bb = 1; bb < NPOW; bb++) { pw *= v; spv[bb][t] = pw; }
        __syncthreads();

        // ---- phase 2: accumulate my feature over the tile ----
        if (t < NF) {
            const float4* pua = (const float4*)&spu[fa][0];
            const float4* pvb = (const float4*)&spv[fb][0];
            #pragma unroll 8
            for (int j = 0; j < TILE / 4; j++) {
                float4 A  = pua[j];
                float4 Bv = pvb[j];
                acc0 = fmaf(A.x, Bv.x, acc0);
                acc1 = fmaf(A.y, Bv.y, acc1);
                acc2 = fmaf(A.z, Bv.z, acc2);
                acc3 = fmaf(A.w, Bv.w, acc3);
            }
        }
    }

    if (t < NF)
        atomicAdd(&g_F[b][t], (acc0 + acc1) + (acc2 + acc3));
}

// ---------------------------------------------------------------------------
// Kernel 2: reduce. One block per batch:
//   out += (w_b/ns^2) * sum_k c_k * F_k^2
// ---------------------------------------------------------------------------
__global__ void __launch_bounds__(256) mmd_reduce(const float* __restrict__ weights,
                                                  const float* __restrict__ num_samples,
                                                  float* __restrict__ out) {
    __shared__ float warp_sums[8];
    int b = blockIdx.x;
    int t = threadIdx.x;

    float val = 0.f;
    if (t < NF) {
        int fa, fb;
        feat_ab(t, fa, fb);
        float c = exp2f((float)(fa + fb)) * c_inv_fact[fa] * c_inv_fact[fb];
        float F = g_F[b][t];
        val = c * F * F;
    }

    #pragma unroll
    for (int o = 16; o > 0; o >>= 1)
        val += __shfl_down_sync(0xFFFFFFFFu, val, o);
    int lane = t & 31, wid = t >> 5;
    if (lane == 0) warp_sums[wid] = val;
    __syncthreads();

    if (t == 0) {
        float bs = 0.f;
        #pragma unroll
        for (int w = 0; w < 8; w++) bs += warp_sums[w];
        float ns = __ldg(&num_samples[b]);
        atomicAdd(out, bs * __ldg(&weights[b]) / (ns * ns));
    }
}

// ---------------------------------------------------------------------------
extern "C" void kernel_launch(void* const* d_in, const int* in_sizes, int n_in,
                              void* d_out, int out_size) {
    const float* X  = (const float*)d_in[0];
    const float* Y  = (const float*)d_in[1];
    const float* w  = (const float*)d_in[2];
    const float* ns = (const float*)d_in[3];
    float* out = (float*)d_out;

    mmd_zero<<<(BATCH * NF + 255) / 256, 256>>>(out);
    mmd_features<<<BATCH * PB, 256>>>(X, Y);
    mmd_reduce<<<BATCH, 256>>>(w, ns, out);
}